// round 1
// baseline (speedup 1.0000x reference)
#include <cuda_runtime.h>
#include <cuda_bf16.h>
#include <math.h>

// ---------------------------------------------------------------------------
// Problem constants
// ---------------------------------------------------------------------------
#define BB 4
#define SS 4096
#define DD 1024
#define HH 16
#define FF 256
#define HD 64
#define NN (BB * SS)          // 16384 rows

// ---------------------------------------------------------------------------
// Scratch (device globals; no allocations allowed)
// ---------------------------------------------------------------------------
__device__ float g_q[NN * DD];
__device__ float g_k[NN * DD];
__device__ float g_v[NN * DD];
__device__ float g_y[NN * DD];
__device__ float g_qp[(size_t)BB * HH * SS * FF];   // [B,H,S,F]
__device__ float g_kp[(size_t)BB * HH * SS * FF];   // [B,H,S,F]
__device__ float g_kv[(size_t)BB * HH * FF * HD];   // [B,H,F,HD]
__device__ float g_ksum[(size_t)BB * HH * FF];      // [B,H,F]

// ---------------------------------------------------------------------------
// f32x2 packed-FMA helpers (FFMA2: full-rate fp32 on sm_103a)
// ---------------------------------------------------------------------------
__device__ __forceinline__ unsigned long long pack2(float lo, float hi) {
    unsigned long long r;
    asm("mov.b64 %0, {%1, %2};" : "=l"(r) : "f"(lo), "f"(hi));
    return r;
}
__device__ __forceinline__ void unpack2(unsigned long long p, float& lo, float& hi) {
    asm("mov.b64 {%0, %1}, %2;" : "=f"(lo), "=f"(hi) : "l"(p));
}
__device__ __forceinline__ unsigned long long ffma2(unsigned long long a,
                                                    unsigned long long b,
                                                    unsigned long long c) {
    unsigned long long d;
    asm("fma.rn.f32x2 %0, %1, %2, %3;" : "=l"(d) : "l"(a), "l"(b), "l"(c));
    return d;
}

__device__ __forceinline__ float softplusf(float x) {
    return fmaxf(x, 0.0f) + log1pf(expf(-fabsf(x)));
}

// ---------------------------------------------------------------------------
// SGEMM-NT with bias: C[n,m] = sum_k A[n,k]*B[m,k] + bias[m]
// A:[N,K] row-major, B:[M,K] row-major. 128x128x16 tile, 256 threads,
// 8x8 microtile packed as 8x4 f32x2 accumulators.
// N,M,K all multiples of 128/16 here; no bounds checks.
// ---------------------------------------------------------------------------
__global__ void __launch_bounds__(256)
sgemm_nt_bias(const float* __restrict__ A, const float* __restrict__ B,
              const float* __restrict__ bias, float* __restrict__ C,
              int N, int M, int K) {
    __shared__ __align__(16) float As[16][132];
    __shared__ __align__(16) float Bs[16][132];

    const int tid = threadIdx.x;
    const int ty = tid >> 4;        // 0..15
    const int tx = tid & 15;        // 0..15
    const int bn = blockIdx.y * 128;
    const int bm = blockIdx.x * 128;

    unsigned long long acc[8][4];
#pragma unroll
    for (int i = 0; i < 8; ++i)
#pragma unroll
        for (int j = 0; j < 4; ++j) acc[i][j] = 0ull;

    const int lr = tid >> 2;           // 0..63
    const int lc = (tid & 3) << 2;     // 0,4,8,12

    const float* Aptr = A + (size_t)(bn + lr) * K + lc;
    const float* Bptr = B + (size_t)(bm + lr) * K + lc;

    for (int k0 = 0; k0 < K; k0 += 16) {
#pragma unroll
        for (int p = 0; p < 2; ++p) {
            float4 a = *(const float4*)(Aptr + (size_t)p * 64 * K + k0);
            int r = lr + p * 64;
            As[lc + 0][r] = a.x; As[lc + 1][r] = a.y;
            As[lc + 2][r] = a.z; As[lc + 3][r] = a.w;
            float4 b = *(const float4*)(Bptr + (size_t)p * 64 * K + k0);
            Bs[lc + 0][r] = b.x; Bs[lc + 1][r] = b.y;
            Bs[lc + 2][r] = b.z; Bs[lc + 3][r] = b.w;
        }
        __syncthreads();
#pragma unroll
        for (int kk = 0; kk < 16; ++kk) {
            float af[8];
            unsigned long long bp[4];
#pragma unroll
            for (int i = 0; i < 8; ++i) af[i] = As[kk][ty * 8 + i];
#pragma unroll
            for (int j = 0; j < 4; ++j)
                bp[j] = *(const unsigned long long*)&Bs[kk][tx * 8 + j * 2];
#pragma unroll
            for (int i = 0; i < 8; ++i) {
                unsigned long long aa = pack2(af[i], af[i]);
#pragma unroll
                for (int j = 0; j < 4; ++j) acc[i][j] = ffma2(aa, bp[j], acc[i][j]);
            }
        }
        __syncthreads();
    }

    // epilogue
    float bv[8];
#pragma unroll
    for (int j = 0; j < 8; ++j) bv[j] = bias[bm + tx * 8 + j];
#pragma unroll
    for (int i = 0; i < 8; ++i) {
        int row = bn + ty * 8 + i;
        float o[8];
#pragma unroll
        for (int j = 0; j < 4; ++j) unpack2(acc[i][j], o[2 * j], o[2 * j + 1]);
#pragma unroll
        for (int j = 0; j < 8; ++j) o[j] += bv[j];
        float* cp = C + (size_t)row * M + bm + tx * 8;
        *(float4*)(cp + 0) = make_float4(o[0], o[1], o[2], o[3]);
        *(float4*)(cp + 4) = make_float4(o[4], o[5], o[6], o[7]);
    }
}

// ---------------------------------------------------------------------------
// phi kernel: outp[b,h,s,f] = softplus( sum_d in[b,s,h*64+d] * rf[h,d,f] )
// grid (S/128, H, B), 256 threads. K=64. F processed in 4 chunks of 64.
// ---------------------------------------------------------------------------
__global__ void __launch_bounds__(256)
phi_kernel(const float* __restrict__ in, const float* __restrict__ rf,
           float* __restrict__ outp) {
    __shared__ __align__(16) float Qs[64][128];   // [d][s] 32KB
    __shared__ __align__(16) float Rs[64][64];    // [d][f-chunk] 16KB

    const int stile = blockIdx.x, h = blockIdx.y, b = blockIdx.z;
    const int tid = threadIdx.x;
    const int ty = tid >> 4, tx = tid & 15;
    const int s0 = stile * 128;
    const int bh = b * HH + h;

    // load Q tile (transposed into smem)
    {
        int s = tid >> 1;
        int dbase = (tid & 1) * 32;
        const float* src = in + ((size_t)(b * SS + s0 + s)) * DD + h * HD + dbase;
#pragma unroll
        for (int q = 0; q < 8; ++q) {
            float4 a = *(const float4*)(src + q * 4);
            int d = dbase + q * 4;
            Qs[d + 0][s] = a.x; Qs[d + 1][s] = a.y;
            Qs[d + 2][s] = a.z; Qs[d + 3][s] = a.w;
        }
    }
    const float* rfh = rf + (size_t)h * HD * FF;

    for (int fc = 0; fc < 4; ++fc) {
        // load rf chunk [64 d][64 f]
        {
            int r = tid >> 2;
            int c = (tid & 3) * 16;
#pragma unroll
            for (int q = 0; q < 4; ++q) {
                *(float4*)&Rs[r][c + q * 4] =
                    *(const float4*)(rfh + (size_t)r * FF + fc * 64 + c + q * 4);
            }
        }
        __syncthreads();

        unsigned long long acc[8][2];
#pragma unroll
        for (int i = 0; i < 8; ++i) { acc[i][0] = 0ull; acc[i][1] = 0ull; }

#pragma unroll 8
        for (int kk = 0; kk < 64; ++kk) {
            float af[8];
#pragma unroll
            for (int i = 0; i < 8; ++i) af[i] = Qs[kk][ty * 8 + i];
            unsigned long long b0 = *(const unsigned long long*)&Rs[kk][tx * 4];
            unsigned long long b1 = *(const unsigned long long*)&Rs[kk][tx * 4 + 2];
#pragma unroll
            for (int i = 0; i < 8; ++i) {
                unsigned long long aa = pack2(af[i], af[i]);
                acc[i][0] = ffma2(aa, b0, acc[i][0]);
                acc[i][1] = ffma2(aa, b1, acc[i][1]);
            }
        }
        // write with softplus
#pragma unroll
        for (int i = 0; i < 8; ++i) {
            int s = s0 + ty * 8 + i;
            float o0, o1, o2, o3;
            unpack2(acc[i][0], o0, o1);
            unpack2(acc[i][1], o2, o3);
            float4 o = make_float4(softplusf(o0), softplusf(o1),
                                   softplusf(o2), softplusf(o3));
            *(float4*)&outp[(((size_t)bh * SS + s)) * FF + fc * 64 + tx * 4] = o;
        }
        __syncthreads();
    }
}

// ---------------------------------------------------------------------------
// zero kernel
// ---------------------------------------------------------------------------
__global__ void zero_kernel(float* __restrict__ p, int n) {
    int i = blockIdx.x * blockDim.x + threadIdx.x;
    if (i < n) p[i] = 0.0f;
}

// ---------------------------------------------------------------------------
// kv kernel: kv[b,h,f,d] += sum_s kp[b,h,s,f] * v[b,s,h*64+d]
//            ksum[b,h,f] += sum_s kp[b,h,s,f]
// grid (8 s-chunks of 512, H, B), 256 threads. atomics at end.
// ---------------------------------------------------------------------------
__global__ void __launch_bounds__(256)
kv_kernel(const float* __restrict__ kp, const float* __restrict__ v,
          float* __restrict__ kv, float* __restrict__ ksum) {
    __shared__ __align__(16) float Ks[32][256];   // [s][f] 32KB
    __shared__ float Vs[32][68];                  // [s][d] padded

    const int chunk = blockIdx.x, h = blockIdx.y, b = blockIdx.z;
    const int tid = threadIdx.x;
    const int ty = tid >> 3;     // f-group: rows ty*8..+8 (0..255)
    const int tx = tid & 7;      // d-group: cols tx*8..+8 (0..63)
    const int bh = b * HH + h;

    float acc[8][8];
#pragma unroll
    for (int i = 0; i < 8; ++i)
#pragma unroll
        for (int j = 0; j < 8; ++j) acc[i][j] = 0.0f;
    float accs[8];
#pragma unroll
    for (int i = 0; i < 8; ++i) accs[i] = 0.0f;

    for (int s0 = chunk * 512; s0 < chunk * 512 + 512; s0 += 32) {
        {
            int r = tid >> 3, c = (tid & 7) * 32;
            const float* src = kp + ((size_t)bh * SS + s0 + r) * FF + c;
#pragma unroll
            for (int q = 0; q < 8; ++q)
                *(float4*)&Ks[r][c + q * 4] = *(const float4*)(src + q * 4);
        }
        {
            int r = tid >> 3, c = (tid & 7) * 8;
            const float* src = v + ((size_t)(b * SS + s0 + r)) * DD + h * HD + c;
            float4 a = *(const float4*)src;
            float4 bb = *(const float4*)(src + 4);
            Vs[r][c + 0] = a.x; Vs[r][c + 1] = a.y; Vs[r][c + 2] = a.z; Vs[r][c + 3] = a.w;
            Vs[r][c + 4] = bb.x; Vs[r][c + 5] = bb.y; Vs[r][c + 6] = bb.z; Vs[r][c + 7] = bb.w;
        }
        __syncthreads();
#pragma unroll 4
        for (int ss = 0; ss < 32; ++ss) {
            float af[8], bf[8];
#pragma unroll
            for (int i = 0; i < 8; ++i) af[i] = Ks[ss][ty * 8 + i];
#pragma unroll
            for (int j = 0; j < 8; ++j) bf[j] = Vs[ss][tx * 8 + j];
#pragma unroll
            for (int i = 0; i < 8; ++i) {
                accs[i] += af[i];
#pragma unroll
                for (int j = 0; j < 8; ++j) acc[i][j] += af[i] * bf[j];
            }
        }
        __syncthreads();
    }

    float* kvp = kv + (size_t)bh * FF * HD;
#pragma unroll
    for (int i = 0; i < 8; ++i)
#pragma unroll
        for (int j = 0; j < 8; ++j)
            atomicAdd(&kvp[(ty * 8 + i) * HD + tx * 8 + j], acc[i][j]);
    if (tx == 0) {
#pragma unroll
        for (int i = 0; i < 8; ++i)
            atomicAdd(&ksum[(size_t)bh * FF + ty * 8 + i], accs[i]);
    }
}

// ---------------------------------------------------------------------------
// out kernel: o[s,d] = (sum_f qp[s,f]*kv[f,d]) / (sum_f qp[s,f]*ksum[f] + 1e-8)
// writes y[b,s,h*64+d]. grid (S/128, H, B), 256 threads.
// ---------------------------------------------------------------------------
__global__ void __launch_bounds__(256)
out_kernel(const float* __restrict__ qp, const float* __restrict__ kvg,
           const float* __restrict__ ksum, float* __restrict__ y) {
    __shared__ float Qps[128][33];               // 16.9KB
    __shared__ __align__(16) float KVs[32][64];  // 8KB
    __shared__ float KSs[32];

    const int stile = blockIdx.x, h = blockIdx.y, b = blockIdx.z;
    const int tid = threadIdx.x;
    const int ty = tid >> 4, tx = tid & 15;      // rows ty*8..+8, cols tx*4..+4
    const int bh = b * HH + h;
    const int s0 = stile * 128;

    float acc[8][4];
#pragma unroll
    for (int i = 0; i < 8; ++i)
#pragma unroll
        for (int j = 0; j < 4; ++j) acc[i][j] = 0.0f;
    float dacc[8];
#pragma unroll
    for (int i = 0; i < 8; ++i) dacc[i] = 0.0f;

    for (int fc = 0; fc < 8; ++fc) {
        {
            int r = tid >> 1, c = (tid & 1) * 16;
            const float* src = qp + ((size_t)bh * SS + s0 + r) * FF + fc * 32 + c;
#pragma unroll
            for (int q = 0; q < 4; ++q) {
                float4 a = *(const float4*)(src + q * 4);
                Qps[r][c + q * 4 + 0] = a.x; Qps[r][c + q * 4 + 1] = a.y;
                Qps[r][c + q * 4 + 2] = a.z; Qps[r][c + q * 4 + 3] = a.w;
            }
        }
        {
            int r = tid >> 3, c = (tid & 7) * 8;
            const float* src = kvg + (size_t)bh * FF * HD + (fc * 32 + r) * HD + c;
            *(float4*)&KVs[r][c + 0] = *(const float4*)(src + 0);
            *(float4*)&KVs[r][c + 4] = *(const float4*)(src + 4);
        }
        if (tid < 32) KSs[tid] = ksum[(size_t)bh * FF + fc * 32 + tid];
        __syncthreads();

#pragma unroll 4
        for (int f = 0; f < 32; ++f) {
            float af[8];
#pragma unroll
            for (int i = 0; i < 8; ++i) af[i] = Qps[ty * 8 + i][f];
            float4 bf = *(const float4*)&KVs[f][tx * 4];
            float ks = KSs[f];
#pragma unroll
            for (int i = 0; i < 8; ++i) {
                acc[i][0] += af[i] * bf.x;
                acc[i][1] += af[i] * bf.y;
                acc[i][2] += af[i] * bf.z;
                acc[i][3] += af[i] * bf.w;
                dacc[i] += af[i] * ks;   // redundant across tx (same ty) but race-free
            }
        }
        __syncthreads();
    }

#pragma unroll
    for (int i = 0; i < 8; ++i) {
        float inv = 1.0f / (dacc[i] + 1e-8f);
        int s = s0 + ty * 8 + i;
        float4 o = make_float4(acc[i][0] * inv, acc[i][1] * inv,
                               acc[i][2] * inv, acc[i][3] * inv);
        *(float4*)&y[((size_t)(b * SS + s)) * DD + h * HD + tx * 4] = o;
    }
}

// ---------------------------------------------------------------------------
// launch
// ---------------------------------------------------------------------------
extern "C" void kernel_launch(void* const* d_in, const int* in_sizes, int n_in,
                              void* d_out, int out_size) {
    const float* x  = (const float*)d_in[0];
    const float* Wq = (const float*)d_in[1];
    const float* bq = (const float*)d_in[2];
    const float* Wk = (const float*)d_in[3];
    const float* bk = (const float*)d_in[4];
    const float* Wv = (const float*)d_in[5];
    const float* bv = (const float*)d_in[6];
    const float* Wo = (const float*)d_in[7];
    const float* bo = (const float*)d_in[8];
    const float* rf = (const float*)d_in[9];
    float* out = (float*)d_out;

    float *pq, *pk, *pv, *py, *pqp, *pkp, *pkv, *pks;
    cudaGetSymbolAddress((void**)&pq,  g_q);
    cudaGetSymbolAddress((void**)&pk,  g_k);
    cudaGetSymbolAddress((void**)&pv,  g_v);
    cudaGetSymbolAddress((void**)&py,  g_y);
    cudaGetSymbolAddress((void**)&pqp, g_qp);
    cudaGetSymbolAddress((void**)&pkp, g_kp);
    cudaGetSymbolAddress((void**)&pkv, g_kv);
    cudaGetSymbolAddress((void**)&pks, g_ksum);

    dim3 gg(DD / 128, NN / 128);   // (8, 128)

    sgemm_nt_bias<<<gg, 256>>>(x, Wq, bq, pq, NN, DD, DD);
    sgemm_nt_bias<<<gg, 256>>>(x, Wk, bk, pk, NN, DD, DD);
    sgemm_nt_bias<<<gg, 256>>>(x, Wv, bv, pv, NN, DD, DD);

    dim3 pg(SS / 128, HH, BB);     // (32, 16, 4)
    phi_kernel<<<pg, 256>>>(pq, rf, pqp);
    phi_kernel<<<pg, 256>>>(pk, rf, pkp);

    zero_kernel<<<(BB * HH * FF * HD + 255) / 256, 256>>>(pkv, BB * HH * FF * HD);
    zero_kernel<<<(BB * HH * FF + 255) / 256, 256>>>(pks, BB * HH * FF);

    kv_kernel<<<dim3(8, HH, BB), 256>>>(pkp, pv, pkv, pks);

    out_kernel<<<pg, 256>>>(pqp, pkv, pks, py);

    sgemm_nt_bias<<<gg, 256>>>(py, Wo, bo, out, NN, DD, DD);
}

// round 4
// speedup vs baseline: 1.4536x; 1.4536x over previous
#include <cuda_runtime.h>
#include <cuda_bf16.h>
#include <math.h>
#include <stdint.h>

// ---------------------------------------------------------------------------
// Problem constants
// ---------------------------------------------------------------------------
#define BB 4
#define SS 4096
#define DD 1024
#define HH 16
#define FF 256
#define HD 64
#define NN (BB * SS)          // 16384 rows
#define GK 1024               // GEMM K

// ---------------------------------------------------------------------------
// Scratch (device globals; no allocations allowed)
// ---------------------------------------------------------------------------
__device__ float g_q[NN * DD];
__device__ float g_k[NN * DD];
__device__ float g_v[NN * DD];
__device__ float g_y[NN * DD];
__device__ float g_qp[(size_t)BB * HH * SS * FF];   // [B,H,S,F]
__device__ float g_kp[(size_t)BB * HH * SS * FF];   // [B,H,S,F]
__device__ float g_kv[(size_t)BB * HH * FF * HD];   // [B,H,F,HD]
__device__ float g_ksum[(size_t)BB * HH * FF];      // [B,H,F]

__device__ __nv_bfloat16 g_xh[NN * DD];
__device__ __nv_bfloat16 g_xl[NN * DD];
__device__ __nv_bfloat16 g_yh[NN * DD];
__device__ __nv_bfloat16 g_yl[NN * DD];
__device__ __nv_bfloat16 g_wh[4 * DD * DD];
__device__ __nv_bfloat16 g_wl[4 * DD * DD];

// ---------------------------------------------------------------------------
// PTX helpers (base-target only: cp.async / ldmatrix / mma.sync)
// ---------------------------------------------------------------------------
__device__ __forceinline__ uint32_t smem_u32(const void* p) {
    return (uint32_t)__cvta_generic_to_shared(p);
}
__device__ __forceinline__ void cp_async16(uint32_t dst, const void* src) {
    asm volatile("cp.async.cg.shared.global [%0], [%1], 16;"
                 :: "r"(dst), "l"(src) : "memory");
}
__device__ __forceinline__ void ldm_x4(uint32_t& r0, uint32_t& r1,
                                       uint32_t& r2, uint32_t& r3, uint32_t addr) {
    asm volatile("ldmatrix.sync.aligned.m8n8.x4.shared.b16 {%0,%1,%2,%3}, [%4];"
                 : "=r"(r0), "=r"(r1), "=r"(r2), "=r"(r3) : "r"(addr));
}
__device__ __forceinline__ void mma16816(float* c, uint32_t a0, uint32_t a1,
                                         uint32_t a2, uint32_t a3,
                                         uint32_t b0, uint32_t b1) {
    asm volatile(
        "mma.sync.aligned.m16n8k16.row.col.f32.bf16.bf16.f32 "
        "{%0,%1,%2,%3}, {%4,%5,%6,%7}, {%8,%9}, {%0,%1,%2,%3};"
        : "+f"(c[0]), "+f"(c[1]), "+f"(c[2]), "+f"(c[3])
        : "r"(a0), "r"(a1), "r"(a2), "r"(a3), "r"(b0), "r"(b1));
}

// ---------------------------------------------------------------------------
// HMMA split-bf16 GEMM-NT: C[n,m] = sum_k A[n,k]*B[m,k] + bias[m]
// A = Ah+Al, B = Bh+Bl (bf16 hi/lo); 3 mma passes (AhBh + AlBh + AhBl).
// 128x128x32 CTA tile, 256 threads (2x4 warps, 64x32 per warp),
// smem rows padded to 80B -> conflict-free ldmatrix, 3-stage cp.async.
// ---------------------------------------------------------------------------
#define KC 32
#define ROWB 80                          // 32 bf16 (64B) padded to 80B
#define TILE_B (128 * ROWB)              // 10240 B per tile
#define STAGE_B (4 * TILE_B)             // Ah, Al, Bh, Bl
#define NSTAGE 3
#define GEMM_DSMEM (NSTAGE * STAGE_B)    // 122880 B

__global__ void __launch_bounds__(256)
gemm_mma(const __nv_bfloat16* __restrict__ Ah, const __nv_bfloat16* __restrict__ Al,
         const __nv_bfloat16* __restrict__ Bh, const __nv_bfloat16* __restrict__ Bl,
         const float* __restrict__ bias, float* __restrict__ C, int Mcols) {
    extern __shared__ char dsm[];
    const uint32_t sbase = smem_u32(dsm);

    const int tid = threadIdx.x;
    const int wid = tid >> 5, lane = tid & 31;
    const int warp_m = wid >> 2;          // 0..1  (64 rows each)
    const int warp_n = wid & 3;           // 0..3  (32 cols each)
    const int bm = blockIdx.x * 128;      // output cols (weight rows)
    const int bn = blockIdx.y * 128;      // output rows

    // ldmatrix lane addressing parts
    const int lrow = lane & 15;
    const int lchunk = (lane >> 4) * 16;  // byte offset for k-half

    float acc[4][4][4];
#pragma unroll
    for (int i = 0; i < 4; ++i)
#pragma unroll
        for (int j = 0; j < 4; ++j)
#pragma unroll
            for (int q = 0; q < 4; ++q) acc[i][j][q] = 0.0f;

    // cp.async mapping: thread t -> row t>>1, two 16B chunks at (t&1)*2
    const int Lrow = tid >> 1;
    const int Lc = (tid & 1) * 2;
    const int arow = bn + Lrow;
    const int brow = bm + Lrow;

    auto issue_chunk = [&](int c, int stage) {
        const int k0 = c * KC;
        const uint32_t st = sbase + stage * STAGE_B;
        const uint32_t soff = (uint32_t)Lrow * ROWB + Lc * 16;
        const __nv_bfloat16* pa = Ah + (size_t)arow * GK + k0 + Lc * 8;
        const __nv_bfloat16* pl = Al + (size_t)arow * GK + k0 + Lc * 8;
        const __nv_bfloat16* pb = Bh + (size_t)brow * GK + k0 + Lc * 8;
        const __nv_bfloat16* pc = Bl + (size_t)brow * GK + k0 + Lc * 8;
#pragma unroll
        for (int q = 0; q < 2; ++q) {
            cp_async16(st + soff + q * 16, pa + q * 8);
            cp_async16(st + TILE_B + soff + q * 16, pl + q * 8);
            cp_async16(st + 2 * TILE_B + soff + q * 16, pb + q * 8);
            cp_async16(st + 3 * TILE_B + soff + q * 16, pc + q * 8);
        }
        asm volatile("cp.async.commit_group;" ::: "memory");
    };

    issue_chunk(0, 0);
    issue_chunk(1, 1);

    const int NCH = GK / KC;       // 32
    for (int c = 0; c < NCH; ++c) {
        asm volatile("cp.async.wait_group 1;" ::: "memory");
        __syncthreads();

        const uint32_t st = sbase + (c % NSTAGE) * STAGE_B;
        const uint32_t a_base = st + (uint32_t)(warp_m * 64 + lrow) * ROWB + lchunk;
        const uint32_t b_base = st + 2 * TILE_B + (uint32_t)(warp_n * 32 + lrow) * ROWB + lchunk;

#pragma unroll
        for (int s = 0; s < 2; ++s) {
            uint32_t ah[4][4], al[4][4];
#pragma unroll
            for (int i = 0; i < 4; ++i) {
                uint32_t ad = a_base + (uint32_t)i * 16 * ROWB + s * 32;
                ldm_x4(ah[i][0], ah[i][1], ah[i][2], ah[i][3], ad);
                ldm_x4(al[i][0], al[i][1], al[i][2], al[i][3], ad + TILE_B);
            }
            uint32_t bh[2][4], bl[2][4];
#pragma unroll
            for (int j2 = 0; j2 < 2; ++j2) {
                uint32_t bd = b_base + (uint32_t)j2 * 16 * ROWB + s * 32;
                ldm_x4(bh[j2][0], bh[j2][1], bh[j2][2], bh[j2][3], bd);
                ldm_x4(bl[j2][0], bl[j2][1], bl[j2][2], bl[j2][3], bd + TILE_B);
            }
#pragma unroll
            for (int i = 0; i < 4; ++i) {
#pragma unroll
                for (int j = 0; j < 4; ++j) {
                    const int j2 = j >> 1, sel = j & 1;
                    // n-tile fragment: {r[sel], r[sel+2]}
                    mma16816(acc[i][j], ah[i][0], ah[i][1], ah[i][2], ah[i][3],
                             bh[j2][sel], bh[j2][sel + 2]);
                    mma16816(acc[i][j], al[i][0], al[i][1], al[i][2], al[i][3],
                             bh[j2][sel], bh[j2][sel + 2]);
                    mma16816(acc[i][j], ah[i][0], ah[i][1], ah[i][2], ah[i][3],
                             bl[j2][sel], bl[j2][sel + 2]);
                }
            }
        }
        __syncthreads();
        if (c + 2 < NCH) issue_chunk(c + 2, (c + 2) % NSTAGE);
    }

    // epilogue: thread l -> rows (l>>2), (l>>2)+8; cols (l&3)*2, +1
#pragma unroll
    for (int i = 0; i < 4; ++i) {
#pragma unroll
        for (int j = 0; j < 4; ++j) {
            const int row0 = bn + warp_m * 64 + i * 16 + (lane >> 2);
            const int col = bm + warp_n * 32 + j * 8 + (lane & 3) * 2;
            const float2 bv = *(const float2*)(bias + col);
            float2 o0, o1;
            o0.x = acc[i][j][0] + bv.x; o0.y = acc[i][j][1] + bv.y;
            o1.x = acc[i][j][2] + bv.x; o1.y = acc[i][j][3] + bv.y;
            *(float2*)(C + (size_t)row0 * Mcols + col) = o0;
            *(float2*)(C + (size_t)(row0 + 8) * Mcols + col) = o1;
        }
    }
}

// ---------------------------------------------------------------------------
// split fp32 -> (bf16 hi, bf16 lo)
// ---------------------------------------------------------------------------
__global__ void __launch_bounds__(256)
split_bf16(const float* __restrict__ in, __nv_bfloat16* __restrict__ hi,
           __nv_bfloat16* __restrict__ lo, int n) {
    int i = (blockIdx.x * 256 + threadIdx.x) * 4;
    if (i >= n) return;
    float4 v = *(const float4*)(in + i);
    float a[4] = {v.x, v.y, v.z, v.w};
    __nv_bfloat16 h[4], l[4];
#pragma unroll
    for (int j = 0; j < 4; ++j) {
        h[j] = __float2bfloat16(a[j]);
        l[j] = __float2bfloat16(a[j] - __bfloat162float(h[j]));
    }
    *(__nv_bfloat162*)(hi + i)     = __nv_bfloat162(h[0], h[1]);
    *(__nv_bfloat162*)(hi + i + 2) = __nv_bfloat162(h[2], h[3]);
    *(__nv_bfloat162*)(lo + i)     = __nv_bfloat162(l[0], l[1]);
    *(__nv_bfloat162*)(lo + i + 2) = __nv_bfloat162(l[2], l[3]);
}

// ---------------------------------------------------------------------------
// f32x2 packed-FMA helpers
// ---------------------------------------------------------------------------
__device__ __forceinline__ unsigned long long pack2(float lo, float hi) {
    unsigned long long r;
    asm("mov.b64 %0, {%1, %2};" : "=l"(r) : "f"(lo), "f"(hi));
    return r;
}
__device__ __forceinline__ void unpack2(unsigned long long p, float& lo, float& hi) {
    asm("mov.b64 {%0, %1}, %2;" : "=f"(lo), "=f"(hi) : "l"(p));
}
__device__ __forceinline__ unsigned long long ffma2(unsigned long long a,
                                                    unsigned long long b,
                                                    unsigned long long c) {
    unsigned long long d;
    asm("fma.rn.f32x2 %0, %1, %2, %3;" : "=l"(d) : "l"(a), "l"(b), "l"(c));
    return d;
}
__device__ __forceinline__ float softplusf(float x) {
    return fmaxf(x, 0.0f) + log1pf(expf(-fabsf(x)));
}

// ---------------------------------------------------------------------------
// phi kernel: outp[b,h,s,f] = softplus( sum_d in[b,s,h*64+d] * rf[h,d,f] )
// ---------------------------------------------------------------------------
__global__ void __launch_bounds__(256)
phi_kernel(const float* __restrict__ in, const float* __restrict__ rf,
           float* __restrict__ outp) {
    __shared__ __align__(16) float Qs[64][128];
    __shared__ __align__(16) float Rs[64][64];

    const int stile = blockIdx.x, h = blockIdx.y, b = blockIdx.z;
    const int tid = threadIdx.x;
    const int ty = tid >> 4, tx = tid & 15;
    const int s0 = stile * 128;
    const int bh = b * HH + h;

    {
        int s = tid >> 1;
        int dbase = (tid & 1) * 32;
        const float* src = in + ((size_t)(b * SS + s0 + s)) * DD + h * HD + dbase;
#pragma unroll
        for (int q = 0; q < 8; ++q) {
            float4 a = *(const float4*)(src + q * 4);
            int d = dbase + q * 4;
            Qs[d + 0][s] = a.x; Qs[d + 1][s] = a.y;
            Qs[d + 2][s] = a.z; Qs[d + 3][s] = a.w;
        }
    }
    const float* rfh = rf + (size_t)h * HD * FF;

    for (int fc = 0; fc < 4; ++fc) {
        {
            int rr = tid >> 2;
            int cc = (tid & 3) * 16;
#pragma unroll
            for (int q = 0; q < 4; ++q) {
                *(float4*)&Rs[rr][cc + q * 4] =
                    *(const float4*)(rfh + (size_t)rr * FF + fc * 64 + cc + q * 4);
            }
        }
        __syncthreads();

        unsigned long long acc[8][2];
#pragma unroll
        for (int i = 0; i < 8; ++i) { acc[i][0] = 0ull; acc[i][1] = 0ull; }

#pragma unroll 8
        for (int kk = 0; kk < 64; ++kk) {
            float af[8];
#pragma unroll
            for (int i = 0; i < 8; ++i) af[i] = Qs[kk][ty * 8 + i];
            unsigned long long b0 = *(const unsigned long long*)&Rs[kk][tx * 4];
            unsigned long long b1 = *(const unsigned long long*)&Rs[kk][tx * 4 + 2];
#pragma unroll
            for (int i = 0; i < 8; ++i) {
                unsigned long long aa = pack2(af[i], af[i]);
                acc[i][0] = ffma2(aa, b0, acc[i][0]);
                acc[i][1] = ffma2(aa, b1, acc[i][1]);
            }
        }
#pragma unroll
        for (int i = 0; i < 8; ++i) {
            int s = s0 + ty * 8 + i;
            float o0, o1, o2, o3;
            unpack2(acc[i][0], o0, o1);
            unpack2(acc[i][1], o2, o3);
            float4 o = make_float4(softplusf(o0), softplusf(o1),
                                   softplusf(o2), softplusf(o3));
            *(float4*)&outp[(((size_t)bh * SS + s)) * FF + fc * 64 + tx * 4] = o;
        }
        __syncthreads();
    }
}

__global__ void zero_kernel(float* __restrict__ p, int n) {
    int i = blockIdx.x * blockDim.x + threadIdx.x;
    if (i < n) p[i] = 0.0f;
}

// ---------------------------------------------------------------------------
// kv kernel
// ---------------------------------------------------------------------------
__global__ void __launch_bounds__(256)
kv_kernel(const float* __restrict__ kp, const float* __restrict__ v,
          float* __restrict__ kv, float* __restrict__ ksum) {
    __shared__ __align__(16) float Ks[32][256];
    __shared__ float Vs[32][68];

    const int chunk = blockIdx.x, h = blockIdx.y, b = blockIdx.z;
    const int tid = threadIdx.x;
    const int ty = tid >> 3;
    const int tx = tid & 7;
    const int bh = b * HH + h;

    float acc[8][8];
#pragma unroll
    for (int i = 0; i < 8; ++i)
#pragma unroll
        for (int j = 0; j < 8; ++j) acc[i][j] = 0.0f;
    float accs[8];
#pragma unroll
    for (int i = 0; i < 8; ++i) accs[i] = 0.0f;

    for (int s0 = chunk * 512; s0 < chunk * 512 + 512; s0 += 32) {
        {
            int rr = tid >> 3, cc = (tid & 7) * 32;
            const float* src = kp + ((size_t)bh * SS + s0 + rr) * FF + cc;
#pragma unroll
            for (int q = 0; q < 8; ++q)
                *(float4*)&Ks[rr][cc + q * 4] = *(const float4*)(src + q * 4);
        }
        {
            int rr = tid >> 3, cc = (tid & 7) * 8;
            const float* src = v + ((size_t)(b * SS + s0 + rr)) * DD + h * HD + cc;
            float4 a = *(const float4*)src;
            float4 bb = *(const float4*)(src + 4);
            Vs[rr][cc + 0] = a.x; Vs[rr][cc + 1] = a.y; Vs[rr][cc + 2] = a.z; Vs[rr][cc + 3] = a.w;
            Vs[rr][cc + 4] = bb.x; Vs[rr][cc + 5] = bb.y; Vs[rr][cc + 6] = bb.z; Vs[rr][cc + 7] = bb.w;
        }
        __syncthreads();
#pragma unroll 4
        for (int ss = 0; ss < 32; ++ss) {
            float af[8], bf[8];
#pragma unroll
            for (int i = 0; i < 8; ++i) af[i] = Ks[ss][ty * 8 + i];
#pragma unroll
            for (int j = 0; j < 8; ++j) bf[j] = Vs[ss][tx * 8 + j];
#pragma unroll
            for (int i = 0; i < 8; ++i) {
                accs[i] += af[i];
#pragma unroll
                for (int j = 0; j < 8; ++j) acc[i][j] += af[i] * bf[j];
            }
        }
        __syncthreads();
    }

    float* kvp = kv + (size_t)bh * FF * HD;
#pragma unroll
    for (int i = 0; i < 8; ++i)
#pragma unroll
        for (int j = 0; j < 8; ++j)
            atomicAdd(&kvp[(ty * 8 + i) * HD + tx * 8 + j], acc[i][j]);
    if (tx == 0) {
#pragma unroll
        for (int i = 0; i < 8; ++i)
            atomicAdd(&ksum[(size_t)bh * FF + ty * 8 + i], accs[i]);
    }
}

// ---------------------------------------------------------------------------
// out kernel
// ---------------------------------------------------------------------------
__global__ void __launch_bounds__(256)
out_kernel(const float* __restrict__ qp, const float* __restrict__ kvg,
           const float* __restrict__ ksum, float* __restrict__ y) {
    __shared__ float Qps[128][33];
    __shared__ __align__(16) float KVs[32][64];
    __shared__ float KSs[32];

    const int stile = blockIdx.x, h = blockIdx.y, b = blockIdx.z;
    const int tid = threadIdx.x;
    const int ty = tid >> 4, tx = tid & 15;
    const int bh = b * HH + h;
    const int s0 = stile * 128;

    float acc[8][4];
#pragma unroll
    for (int i = 0; i < 8; ++i)
#pragma unroll
        for (int j = 0; j < 4; ++j) acc[i][j] = 0.0f;
    float dacc[8];
#pragma unroll
    for (int i = 0; i < 8; ++i) dacc[i] = 0.0f;

    for (int fc = 0; fc < 8; ++fc) {
        {
            int rr = tid >> 1, cc = (tid & 1) * 16;
            const float* src = qp + ((size_t)bh * SS + s0 + rr) * FF + fc * 32 + cc;
#pragma unroll
            for (int q = 0; q < 4; ++q) {
                float4 a = *(const float4*)(src + q * 4);
                Qps[rr][cc + q * 4 + 0] = a.x; Qps[rr][cc + q * 4 + 1] = a.y;
                Qps[rr][cc + q * 4 + 2] = a.z; Qps[rr][cc + q * 4 + 3] = a.w;
            }
        }
        {
            int rr = tid >> 3, cc = (tid & 7) * 8;
            const float* src = kvg + (size_t)bh * FF * HD + (fc * 32 + rr) * HD + cc;
            *(float4*)&KVs[rr][cc + 0] = *(const float4*)(src + 0);
            *(float4*)&KVs[rr][cc + 4] = *(const float4*)(src + 4);
        }
        if (tid < 32) KSs[tid] = ksum[(size_t)bh * FF + fc * 32 + tid];
        __syncthreads();

#pragma unroll 4
        for (int f = 0; f < 32; ++f) {
            float af[8];
#pragma unroll
            for (int i = 0; i < 8; ++i) af[i] = Qps[ty * 8 + i][f];
            float4 bf = *(const float4*)&KVs[f][tx * 4];
            float ks = KSs[f];
#pragma unroll
            for (int i = 0; i < 8; ++i) {
                acc[i][0] += af[i] * bf.x;
                acc[i][1] += af[i] * bf.y;
                acc[i][2] += af[i] * bf.z;
                acc[i][3] += af[i] * bf.w;
                dacc[i] += af[i] * ks;
            }
        }
        __syncthreads();
    }

#pragma unroll
    for (int i = 0; i < 8; ++i) {
        float inv = 1.0f / (dacc[i] + 1e-8f);
        int s = s0 + ty * 8 + i;
        float4 o = make_float4(acc[i][0] * inv, acc[i][1] * inv,
                               acc[i][2] * inv, acc[i][3] * inv);
        *(float4*)&y[((size_t)(b * SS + s)) * DD + h * HD + tx * 4] = o;
    }
}

// ---------------------------------------------------------------------------
// launch
// ---------------------------------------------------------------------------
extern "C" void kernel_launch(void* const* d_in, const int* in_sizes, int n_in,
                              void* d_out, int out_size) {
    const float* x  = (const float*)d_in[0];
    const float* Wq = (const float*)d_in[1];
    const float* bq = (const float*)d_in[2];
    const float* Wk = (const float*)d_in[3];
    const float* bk = (const float*)d_in[4];
    const float* Wv = (const float*)d_in[5];
    const float* bv = (const float*)d_in[6];
    const float* Wo = (const float*)d_in[7];
    const float* bo = (const float*)d_in[8];
    const float* rf = (const float*)d_in[9];
    float* out = (float*)d_out;

    float *pq, *pk, *pv, *py, *pqp, *pkp, *pkv, *pks;
    __nv_bfloat16 *pxh, *pxl, *pyh, *pyl, *pwh, *pwl;
    cudaGetSymbolAddress((void**)&pq,  g_q);
    cudaGetSymbolAddress((void**)&pk,  g_k);
    cudaGetSymbolAddress((void**)&pv,  g_v);
    cudaGetSymbolAddress((void**)&py,  g_y);
    cudaGetSymbolAddress((void**)&pqp, g_qp);
    cudaGetSymbolAddress((void**)&pkp, g_kp);
    cudaGetSymbolAddress((void**)&pkv, g_kv);
    cudaGetSymbolAddress((void**)&pks, g_ksum);
    cudaGetSymbolAddress((void**)&pxh, g_xh);
    cudaGetSymbolAddress((void**)&pxl, g_xl);
    cudaGetSymbolAddress((void**)&pyh, g_yh);
    cudaGetSymbolAddress((void**)&pyl, g_yl);
    cudaGetSymbolAddress((void**)&pwh, g_wh);
    cudaGetSymbolAddress((void**)&pwl, g_wl);

    cudaFuncSetAttribute(gemm_mma, cudaFuncAttributeMaxDynamicSharedMemorySize,
                         GEMM_DSMEM);

    const int WSZ = DD * DD;

    // split x and weights into bf16 hi/lo
    split_bf16<<<NN * DD / 4 / 256, 256>>>(x, pxh, pxl, NN * DD);
    split_bf16<<<WSZ / 4 / 256, 256>>>(Wq, pwh + 0 * WSZ, pwl + 0 * WSZ, WSZ);
    split_bf16<<<WSZ / 4 / 256, 256>>>(Wk, pwh + 1 * WSZ, pwl + 1 * WSZ, WSZ);
    split_bf16<<<WSZ / 4 / 256, 256>>>(Wv, pwh + 2 * WSZ, pwl + 2 * WSZ, WSZ);
    split_bf16<<<WSZ / 4 / 256, 256>>>(Wo, pwh + 3 * WSZ, pwl + 3 * WSZ, WSZ);

    dim3 gg(DD / 128, NN / 128);   // (8, 128)
    gemm_mma<<<gg, 256, GEMM_DSMEM>>>(pxh, pxl, pwh + 0 * WSZ, pwl + 0 * WSZ, bq, pq, DD);
    gemm_mma<<<gg, 256, GEMM_DSMEM>>>(pxh, pxl, pwh + 1 * WSZ, pwl + 1 * WSZ, bk, pk, DD);
    gemm_mma<<<gg, 256, GEMM_DSMEM>>>(pxh, pxl, pwh + 2 * WSZ, pwl + 2 * WSZ, bv, pv, DD);

    dim3 pg(SS / 128, HH, BB);     // (32, 16, 4)
    phi_kernel<<<pg, 256>>>(pq, rf, pqp);
    phi_kernel<<<pg, 256>>>(pk, rf, pkp);

    zero_kernel<<<(BB * HH * FF * HD + 255) / 256, 256>>>(pkv, BB * HH * FF * HD);
    zero_kernel<<<(BB * HH * FF + 255) / 256, 256>>>(pks, BB * HH * FF);

    kv_kernel<<<dim3(8, HH, BB), 256>>>(pkp, pv, pkv, pks);

    out_kernel<<<pg, 256>>>(pqp, pkv, pks, py);

    split_bf16<<<NN * DD / 4 / 256, 256>>>(py, pyh, pyl, NN * DD);
    gemm_mma<<<gg, 256, GEMM_DSMEM>>>(pyh, pyl, pwh + 3 * WSZ, pwl + 3 * WSZ, bo, out, DD);
}

// round 6
// speedup vs baseline: 1.6150x; 1.1111x over previous
#include <cuda_runtime.h>
#include <cuda_bf16.h>
#include <math.h>
#include <stdint.h>

// ---------------------------------------------------------------------------
// Problem constants
// ---------------------------------------------------------------------------
#define BB 4
#define SS 4096
#define DD 1024
#define HH 16
#define FF 256
#define HD 64
#define NN (BB * SS)          // 16384 rows
#define GK 1024               // GEMM K

// ---------------------------------------------------------------------------
// Scratch (device globals; no allocations allowed)
// ---------------------------------------------------------------------------
__device__ __nv_bfloat16 g_xh[NN * DD];
__device__ __nv_bfloat16 g_xl[NN * DD];
__device__ __nv_bfloat16 g_wh[4 * DD * DD];
__device__ __nv_bfloat16 g_wl[4 * DD * DD];
__device__ __nv_bfloat16 g_rfh[HH * HD * FF];
__device__ __nv_bfloat16 g_rfl[HH * HD * FF];

__device__ __nv_bfloat16 g_qh[NN * DD];
__device__ __nv_bfloat16 g_ql[NN * DD];
__device__ __nv_bfloat16 g_kh[NN * DD];
__device__ __nv_bfloat16 g_kl[NN * DD];
__device__ __nv_bfloat16 g_vh[NN * DD];
__device__ __nv_bfloat16 g_vl[NN * DD];
__device__ __nv_bfloat16 g_yh[NN * DD];
__device__ __nv_bfloat16 g_yl[NN * DD];

__device__ __nv_bfloat16 g_qph[(size_t)BB * HH * SS * FF];
__device__ __nv_bfloat16 g_qpl[(size_t)BB * HH * SS * FF];
__device__ __nv_bfloat16 g_kph[(size_t)BB * HH * SS * FF];
__device__ __nv_bfloat16 g_kpl[(size_t)BB * HH * SS * FF];

__device__ float g_kv[(size_t)BB * HH * FF * HD];     // fp32 (atomics)
__device__ __nv_bfloat16 g_kvh[(size_t)BB * HH * FF * HD];
__device__ __nv_bfloat16 g_kvl[(size_t)BB * HH * FF * HD];
__device__ float g_ksum[(size_t)BB * HH * FF];

// ---------------------------------------------------------------------------
// PTX helpers (base-target: cp.async / ldmatrix / mma.sync)
// ---------------------------------------------------------------------------
__device__ __forceinline__ uint32_t smem_u32(const void* p) {
    return (uint32_t)__cvta_generic_to_shared(p);
}
__device__ __forceinline__ void cp_async16(uint32_t dst, const void* src) {
    asm volatile("cp.async.cg.shared.global [%0], [%1], 16;"
                 :: "r"(dst), "l"(src) : "memory");
}
__device__ __forceinline__ void ldm_x4(uint32_t& r0, uint32_t& r1,
                                       uint32_t& r2, uint32_t& r3, uint32_t addr) {
    asm volatile("ldmatrix.sync.aligned.m8n8.x4.shared.b16 {%0,%1,%2,%3}, [%4];"
                 : "=r"(r0), "=r"(r1), "=r"(r2), "=r"(r3) : "r"(addr));
}
__device__ __forceinline__ void ldm_x4_t(uint32_t& r0, uint32_t& r1,
                                         uint32_t& r2, uint32_t& r3, uint32_t addr) {
    asm volatile("ldmatrix.sync.aligned.m8n8.x4.trans.shared.b16 {%0,%1,%2,%3}, [%4];"
                 : "=r"(r0), "=r"(r1), "=r"(r2), "=r"(r3) : "r"(addr));
}
__device__ __forceinline__ void mma16816(float* c, uint32_t a0, uint32_t a1,
                                         uint32_t a2, uint32_t a3,
                                         uint32_t b0, uint32_t b1) {
    asm volatile(
        "mma.sync.aligned.m16n8k16.row.col.f32.bf16.bf16.f32 "
        "{%0,%1,%2,%3}, {%4,%5,%6,%7}, {%8,%9}, {%0,%1,%2,%3};"
        : "+f"(c[0]), "+f"(c[1]), "+f"(c[2]), "+f"(c[3])
        : "r"(a0), "r"(a1), "r"(a2), "r"(a3), "r"(b0), "r"(b1));
}
// trans ldmatrix per-lane address for [K,N] (or [K,M]) row-major smem storage:
// lanes 0-7: rows k0..k0+7 at col0; 8-15: same rows at col0+8;
// 16-23: rows k0+8.. at col0; 24-31: rows k0+8.. at col0+8.
__device__ __forceinline__ uint32_t taddr(uint32_t base, int stride,
                                          int k0, int col0, int lane) {
    int g = lane >> 3, r = lane & 7;
    return base + (uint32_t)((k0 + ((g >> 1) << 3) + r) * stride
                             + (col0 + ((g & 1) << 3)) * 2);
}
__device__ __forceinline__ void split2(float v, __nv_bfloat16& h, __nv_bfloat16& l) {
    h = __float2bfloat16(v);
    l = __float2bfloat16(v - __bfloat162float(h));
}
__device__ __forceinline__ float softplusf(float x) {
    return fmaxf(x, 0.0f) + log1pf(expf(-fabsf(x)));
}

// ---------------------------------------------------------------------------
// HMMA split-bf16 GEMM-NT core (R4-validated): 128x128x32 CTA tile
// ---------------------------------------------------------------------------
#define KC 32
#define ROWB 80
#define TILE_B (128 * ROWB)
#define STAGE_B (4 * TILE_B)
#define NSTAGE 3
#define GEMM_DSMEM (NSTAGE * STAGE_B)    // 122880 B

template <int SPLIT_OUT>
__device__ __forceinline__ void gemm_core(
    const __nv_bfloat16* __restrict__ Ah, const __nv_bfloat16* __restrict__ Al,
    const __nv_bfloat16* __restrict__ Bh, const __nv_bfloat16* __restrict__ Bl,
    const float* __restrict__ bias, float* __restrict__ C,
    __nv_bfloat16* __restrict__ Ch, __nv_bfloat16* __restrict__ Cl, int Mcols) {
    extern __shared__ char dsm[];
    const uint32_t sbase = smem_u32(dsm);

    const int tid = threadIdx.x;
    const int wid = tid >> 5, lane = tid & 31;
    const int warp_m = wid >> 2;
    const int warp_n = wid & 3;
    const int bm = blockIdx.x * 128;
    const int bn = blockIdx.y * 128;

    const int lrow = lane & 15;
    const int lchunk = (lane >> 4) * 16;

    float acc[4][4][4];
#pragma unroll
    for (int i = 0; i < 4; ++i)
#pragma unroll
        for (int j = 0; j < 4; ++j)
#pragma unroll
            for (int q = 0; q < 4; ++q) acc[i][j][q] = 0.0f;

    const int Lrow = tid >> 1;
    const int Lc = (tid & 1) * 2;
    const int arow = bn + Lrow;
    const int brow = bm + Lrow;

    auto issue_chunk = [&](int c, int stage) {
        const int k0 = c * KC;
        const uint32_t st = sbase + stage * STAGE_B;
        const uint32_t soff = (uint32_t)Lrow * ROWB + Lc * 16;
        const __nv_bfloat16* pa = Ah + (size_t)arow * GK + k0 + Lc * 8;
        const __nv_bfloat16* pl = Al + (size_t)arow * GK + k0 + Lc * 8;
        const __nv_bfloat16* pb = Bh + (size_t)brow * GK + k0 + Lc * 8;
        const __nv_bfloat16* pc = Bl + (size_t)brow * GK + k0 + Lc * 8;
#pragma unroll
        for (int q = 0; q < 2; ++q) {
            cp_async16(st + soff + q * 16, pa + q * 8);
            cp_async16(st + TILE_B + soff + q * 16, pl + q * 8);
            cp_async16(st + 2 * TILE_B + soff + q * 16, pb + q * 8);
            cp_async16(st + 3 * TILE_B + soff + q * 16, pc + q * 8);
        }
        asm volatile("cp.async.commit_group;" ::: "memory");
    };

    issue_chunk(0, 0);
    issue_chunk(1, 1);

    const int NCH = GK / KC;
    for (int c = 0; c < NCH; ++c) {
        asm volatile("cp.async.wait_group 1;" ::: "memory");
        __syncthreads();

        const uint32_t st = sbase + (c % NSTAGE) * STAGE_B;
        const uint32_t a_base = st + (uint32_t)(warp_m * 64 + lrow) * ROWB + lchunk;
        const uint32_t b_base = st + 2 * TILE_B + (uint32_t)(warp_n * 32 + lrow) * ROWB + lchunk;

#pragma unroll
        for (int s = 0; s < 2; ++s) {
            uint32_t ah[4][4], al[4][4];
#pragma unroll
            for (int i = 0; i < 4; ++i) {
                uint32_t ad = a_base + (uint32_t)i * 16 * ROWB + s * 32;
                ldm_x4(ah[i][0], ah[i][1], ah[i][2], ah[i][3], ad);
                ldm_x4(al[i][0], al[i][1], al[i][2], al[i][3], ad + TILE_B);
            }
            uint32_t bh[2][4], bl[2][4];
#pragma unroll
            for (int j2 = 0; j2 < 2; ++j2) {
                uint32_t bd = b_base + (uint32_t)j2 * 16 * ROWB + s * 32;
                ldm_x4(bh[j2][0], bh[j2][1], bh[j2][2], bh[j2][3], bd);
                ldm_x4(bl[j2][0], bl[j2][1], bl[j2][2], bl[j2][3], bd + TILE_B);
            }
#pragma unroll
            for (int i = 0; i < 4; ++i) {
#pragma unroll
                for (int j = 0; j < 4; ++j) {
                    const int j2 = j >> 1, sel = j & 1;
                    mma16816(acc[i][j], ah[i][0], ah[i][1], ah[i][2], ah[i][3],
                             bh[j2][sel], bh[j2][sel + 2]);
                    mma16816(acc[i][j], al[i][0], al[i][1], al[i][2], al[i][3],
                             bh[j2][sel], bh[j2][sel + 2]);
                    mma16816(acc[i][j], ah[i][0], ah[i][1], ah[i][2], ah[i][3],
                             bl[j2][sel], bl[j2][sel + 2]);
                }
            }
        }
        __syncthreads();
        if (c + 2 < NCH) issue_chunk(c + 2, (c + 2) % NSTAGE);
    }

#pragma unroll
    for (int i = 0; i < 4; ++i) {
#pragma unroll
        for (int j = 0; j < 4; ++j) {
            const int row0 = bn + warp_m * 64 + i * 16 + (lane >> 2);
            const int col = bm + warp_n * 32 + j * 8 + (lane & 3) * 2;
            const float2 bv = *(const float2*)(bias + col);
            float o00 = acc[i][j][0] + bv.x, o01 = acc[i][j][1] + bv.y;
            float o10 = acc[i][j][2] + bv.x, o11 = acc[i][j][3] + bv.y;
            if (SPLIT_OUT) {
                __nv_bfloat16 h0, l0, h1, l1;
                split2(o00, h0, l0); split2(o01, h1, l1);
                *(__nv_bfloat162*)(Ch + (size_t)row0 * Mcols + col) = __nv_bfloat162(h0, h1);
                *(__nv_bfloat162*)(Cl + (size_t)row0 * Mcols + col) = __nv_bfloat162(l0, l1);
                split2(o10, h0, l0); split2(o11, h1, l1);
                *(__nv_bfloat162*)(Ch + (size_t)(row0 + 8) * Mcols + col) = __nv_bfloat162(h0, h1);
                *(__nv_bfloat162*)(Cl + (size_t)(row0 + 8) * Mcols + col) = __nv_bfloat162(l0, l1);
            } else {
                *(float2*)(C + (size_t)row0 * Mcols + col) = make_float2(o00, o01);
                *(float2*)(C + (size_t)(row0 + 8) * Mcols + col) = make_float2(o10, o11);
            }
        }
    }
}

__global__ void __launch_bounds__(256)
gemm_mma_f32(const __nv_bfloat16* Ah, const __nv_bfloat16* Al,
             const __nv_bfloat16* Bh, const __nv_bfloat16* Bl,
             const float* bias, float* C, int Mcols) {
    gemm_core<0>(Ah, Al, Bh, Bl, bias, C, nullptr, nullptr, Mcols);
}
__global__ void __launch_bounds__(256)
gemm_mma_split(const __nv_bfloat16* Ah, const __nv_bfloat16* Al,
               const __nv_bfloat16* Bh, const __nv_bfloat16* Bl,
               const float* bias, __nv_bfloat16* Ch, __nv_bfloat16* Cl, int Mcols) {
    gemm_core<1>(Ah, Al, Bh, Bl, bias, nullptr, Ch, Cl, Mcols);
}

// ---------------------------------------------------------------------------
// phi_mma: qp[b,h,s,f] = softplus( sum_d q[s,d]*rf[d,f] ), split-bf16 out
// grid (32 stile, 2 fchunk, 64 bh), 256 thr. CTA tile: 128s x 128f, K=64.
// ---------------------------------------------------------------------------
#define PH_QS 144      // q tile row stride  (64d*2 + 16)
#define PH_RS 272      // rf chunk row stride (128f*2 + 16)
#define PH_QH 0
#define PH_QL (128 * PH_QS)                 // 18432
#define PH_RFH (2 * 128 * PH_QS)            // 36864
#define PH_RFL (PH_RFH + 64 * PH_RS)        // 54272
#define PH_DSMEM (PH_RFL + 64 * PH_RS)      // 71680

__global__ void __launch_bounds__(256)
phi_mma(const __nv_bfloat16* __restrict__ Qh, const __nv_bfloat16* __restrict__ Ql,
        const __nv_bfloat16* __restrict__ RFh, const __nv_bfloat16* __restrict__ RFl,
        __nv_bfloat16* __restrict__ Ph, __nv_bfloat16* __restrict__ Pl) {
    extern __shared__ char dsm[];
    const uint32_t sb = smem_u32(dsm);
    const int tid = threadIdx.x;
    const int wid = tid >> 5, lane = tid & 31;
    const int stile = blockIdx.x, fc = blockIdx.y, bh = blockIdx.z;
    const int b = bh >> 4, h = bh & 15;
    const int s0 = stile * 128;

    {
        const int r = tid >> 1, c0 = (tid & 1) * 4;
        const __nv_bfloat16* ph = Qh + ((size_t)(b * SS + s0 + r)) * DD + h * HD + c0 * 8;
        const __nv_bfloat16* pl = Ql + ((size_t)(b * SS + s0 + r)) * DD + h * HD + c0 * 8;
        const uint32_t so = sb + (uint32_t)r * PH_QS + c0 * 16;
#pragma unroll
        for (int q = 0; q < 4; ++q) {
            cp_async16(so + q * 16, ph + q * 8);
            cp_async16(so + PH_QL + q * 16, pl + q * 8);
        }
    }
    {
        const int r = tid >> 2, c0 = (tid & 3) * 4;
        const __nv_bfloat16* ph = RFh + (size_t)h * HD * FF + (size_t)r * FF + fc * 128 + c0 * 8;
        const __nv_bfloat16* pl = RFl + (size_t)h * HD * FF + (size_t)r * FF + fc * 128 + c0 * 8;
        const uint32_t so = sb + PH_RFH + (uint32_t)r * PH_RS + c0 * 16;
#pragma unroll
        for (int q = 0; q < 4; ++q) {
            cp_async16(so + q * 16, ph + q * 8);
            cp_async16(so + (PH_RFL - PH_RFH) + q * 16, pl + q * 8);
        }
    }
    asm volatile("cp.async.commit_group;" ::: "memory");
    asm volatile("cp.async.wait_group 0;" ::: "memory");
    __syncthreads();

    float acc[16][4];
#pragma unroll
    for (int j = 0; j < 16; ++j)
#pragma unroll
        for (int q = 0; q < 4; ++q) acc[j][q] = 0.0f;

    const int lrow = lane & 15, lch = (lane >> 4) * 16;
    const uint32_t a_base = sb + (uint32_t)(wid * 16 + lrow) * PH_QS + lch;

#pragma unroll
    for (int ks = 0; ks < 4; ++ks) {
        uint32_t ah[4], al[4];
        uint32_t ad = a_base + ks * 32;
        ldm_x4(ah[0], ah[1], ah[2], ah[3], ad);
        ldm_x4(al[0], al[1], al[2], al[3], ad + PH_QL);
#pragma unroll
        for (int ft = 0; ft < 8; ++ft) {
            uint32_t bh4[4], bl4[4];
            uint32_t bd = taddr(sb + PH_RFH, PH_RS, ks * 16, ft * 16, lane);
            ldm_x4_t(bh4[0], bh4[1], bh4[2], bh4[3], bd);
            ldm_x4_t(bl4[0], bl4[1], bl4[2], bl4[3], bd + (PH_RFL - PH_RFH));
#pragma unroll
            for (int sel = 0; sel < 2; ++sel) {
                const int j = ft * 2 + sel;
                mma16816(acc[j], ah[0], ah[1], ah[2], ah[3], bh4[sel], bh4[sel + 2]);
                mma16816(acc[j], al[0], al[1], al[2], al[3], bh4[sel], bh4[sel + 2]);
                mma16816(acc[j], ah[0], ah[1], ah[2], ah[3], bl4[sel], bl4[sel + 2]);
            }
        }
    }

    const int r0 = wid * 16 + (lane >> 2);
#pragma unroll
    for (int j = 0; j < 16; ++j) {
        const int col = fc * 128 + j * 8 + (lane & 3) * 2;
        float s00 = softplusf(acc[j][0]), s01 = softplusf(acc[j][1]);
        float s10 = softplusf(acc[j][2]), s11 = softplusf(acc[j][3]);
        __nv_bfloat16 h0, l0, h1, l1;
        size_t o0 = ((size_t)bh * SS + s0 + r0) * FF + col;
        size_t o1 = ((size_t)bh * SS + s0 + r0 + 8) * FF + col;
        split2(s00, h0, l0); split2(s01, h1, l1);
        *(__nv_bfloat162*)(Ph + o0) = __nv_bfloat162(h0, h1);
        *(__nv_bfloat162*)(Pl + o0) = __nv_bfloat162(l0, l1);
        split2(s10, h0, l0); split2(s11, h1, l1);
        *(__nv_bfloat162*)(Ph + o1) = __nv_bfloat162(h0, h1);
        *(__nv_bfloat162*)(Pl + o1) = __nv_bfloat162(l0, l1);
    }
}

// ---------------------------------------------------------------------------
// kv_mma: kv[f,d] += sum_s kp[s,f]*v[s,d]; ksum[f] += sum_s kp[s,f]
// grid (8 s-chunk, 16 h, 4 b), 256 thr. CTA: 256f x 64d, s-chunk 512.
// ---------------------------------------------------------------------------
#define KV_KS 528
#define KV_VS 144
#define KV_KH 0
#define KV_KL 16896
#define KV_VH 33792
#define KV_VL 38400
#define KV_STG 43008
#define KV_DSMEM (2 * KV_STG)   // 86016

__global__ void __launch_bounds__(256)
kv_mma(const __nv_bfloat16* __restrict__ Kph, const __nv_bfloat16* __restrict__ Kpl,
       const __nv_bfloat16* __restrict__ Vh, const __nv_bfloat16* __restrict__ Vl,
       float* __restrict__ kv, float* __restrict__ ksum) {
    extern __shared__ char dsm[];
    const uint32_t sb = smem_u32(dsm);
    const int tid = threadIdx.x;
    const int wid = tid >> 5, lane = tid & 31;
    const int chunk = blockIdx.x, h = blockIdx.y, b = blockIdx.z;
    const int bh = b * HH + h;
    const int sbase0 = chunk * 512;

    auto issue = [&](int t, int stg) {
        const int s0 = sbase0 + t * 32;
        const uint32_t st = sb + stg * KV_STG;
        const int r = tid >> 3;
        {
            const int c0 = (tid & 7) * 4;
            const __nv_bfloat16* ph = Kph + ((size_t)bh * SS + s0 + r) * FF + c0 * 8;
            const __nv_bfloat16* pl = Kpl + ((size_t)bh * SS + s0 + r) * FF + c0 * 8;
            const uint32_t so = st + (uint32_t)r * KV_KS + c0 * 16;
#pragma unroll
            for (int q = 0; q < 4; ++q) {
                cp_async16(so + q * 16, ph + q * 8);
                cp_async16(so + KV_KL + q * 16, pl + q * 8);
            }
        }
        {
            const int c = tid & 7;
            const __nv_bfloat16* ph = Vh + ((size_t)(b * SS + s0 + r)) * DD + h * HD + c * 8;
            const __nv_bfloat16* pl = Vl + ((size_t)(b * SS + s0 + r)) * DD + h * HD + c * 8;
            cp_async16(st + KV_VH + (uint32_t)r * KV_VS + c * 16, ph);
            cp_async16(st + KV_VL + (uint32_t)r * KV_VS + c * 16, pl);
        }
        asm volatile("cp.async.commit_group;" ::: "memory");
    };

    float acc[2][8][4];
#pragma unroll
    for (int i = 0; i < 2; ++i)
#pragma unroll
        for (int j = 0; j < 8; ++j)
#pragma unroll
            for (int q = 0; q < 4; ++q) acc[i][j][q] = 0.0f;
    float ks_acc = 0.0f;

    issue(0, 0);
    for (int t = 0; t < 16; ++t) {
        if (t + 1 < 16) issue(t + 1, (t + 1) & 1);
        if (t + 1 < 16) { asm volatile("cp.async.wait_group 1;" ::: "memory"); }
        else            { asm volatile("cp.async.wait_group 0;" ::: "memory"); }
        __syncthreads();
        const uint32_t st = sb + (t & 1) * KV_STG;

        {
            const uint32_t c2 = tid * 2;
#pragma unroll 8
            for (int s = 0; s < 32; ++s) {
                __nv_bfloat16 vh_, vl_;
                asm volatile("ld.shared.b16 %0, [%1];" : "=h"(*(uint16_t*)&vh_)
                             : "r"(st + KV_KH + s * KV_KS + c2));
                asm volatile("ld.shared.b16 %0, [%1];" : "=h"(*(uint16_t*)&vl_)
                             : "r"(st + KV_KL + s * KV_KS + c2));
                ks_acc += __bfloat162float(vh_) + __bfloat162float(vl_);
            }
        }

#pragma unroll
        for (int ks = 0; ks < 2; ++ks) {
            uint32_t ah[2][4], al[2][4];
#pragma unroll
            for (int mt = 0; mt < 2; ++mt) {
                uint32_t ad = taddr(st + KV_KH, KV_KS, ks * 16, wid * 32 + mt * 16, lane);
                ldm_x4_t(ah[mt][0], ah[mt][1], ah[mt][2], ah[mt][3], ad);
                ldm_x4_t(al[mt][0], al[mt][1], al[mt][2], al[mt][3], ad + KV_KL);
            }
#pragma unroll
            for (int dg = 0; dg < 4; ++dg) {
                uint32_t bh4[4], bl4[4];
                uint32_t bd = taddr(st + KV_VH, KV_VS, ks * 16, dg * 16, lane);
                ldm_x4_t(bh4[0], bh4[1], bh4[2], bh4[3], bd);
                ldm_x4_t(bl4[0], bl4[1], bl4[2], bl4[3], bd + (KV_VL - KV_VH));
#pragma unroll
                for (int mt = 0; mt < 2; ++mt) {
#pragma unroll
                    for (int sel = 0; sel < 2; ++sel) {
                        const int j = dg * 2 + sel;
                        mma16816(acc[mt][j], ah[mt][0], ah[mt][1], ah[mt][2], ah[mt][3],
                                 bh4[sel], bh4[sel + 2]);
                        mma16816(acc[mt][j], al[mt][0], al[mt][1], al[mt][2], al[mt][3],
                                 bh4[sel], bh4[sel + 2]);
                        mma16816(acc[mt][j], ah[mt][0], ah[mt][1], ah[mt][2], ah[mt][3],
                                 bl4[sel], bl4[sel + 2]);
                    }
                }
            }
        }
        __syncthreads();
    }

    float* kvp = kv + (size_t)bh * FF * HD;
#pragma unroll
    for (int mt = 0; mt < 2; ++mt) {
        const int f0 = wid * 32 + mt * 16 + (lane >> 2);
#pragma unroll
        for (int j = 0; j < 8; ++j) {
            const int d0 = j * 8 + (lane & 3) * 2;
            atomicAdd(&kvp[f0 * HD + d0],       acc[mt][j][0]);
            atomicAdd(&kvp[f0 * HD + d0 + 1],   acc[mt][j][1]);
            atomicAdd(&kvp[(f0 + 8) * HD + d0],     acc[mt][j][2]);
            atomicAdd(&kvp[(f0 + 8) * HD + d0 + 1], acc[mt][j][3]);
        }
    }
    atomicAdd(&ksum[(size_t)bh * FF + tid], ks_acc);
}

// ---------------------------------------------------------------------------
// out_mma: y[s,d] = (sum_f qp[s,f]*kv[f,d]) / (sum_f qp[s,f]*ksum[f] + 1e-8)
// grid (32 stile, 16 h, 4 b), 256 thr. CTA: 128s x 64d, K=F=256.
// kv (h+l) resident in smem; q' chunks double-buffered.
// FIXED vs R5: issue_q(c+2) moved AFTER the consumption barrier (the R5
// version issued it at the top of iteration c, overwriting the stage being
// consumed -> data race -> rel_err 2.9e-2).
// ---------------------------------------------------------------------------
#define OM_KVS 144
#define OM_QS 80
#define OM_KVH 0
#define OM_KVL 36864
#define OM_Q 73728
#define OM_QSTG 20480                 // per stage: qh(10240)+ql(10240)
#define OM_KSUM (OM_Q + 2 * OM_QSTG)  // 114688
#define OM_DEN (OM_KSUM + 1024)       // 115712
#define OM_DSMEM (OM_DEN + 512)       // 116224

__global__ void __launch_bounds__(256)
out_mma(const __nv_bfloat16* __restrict__ Qph, const __nv_bfloat16* __restrict__ Qpl,
        const __nv_bfloat16* __restrict__ KVh, const __nv_bfloat16* __restrict__ KVl,
        const float* __restrict__ ksum,
        __nv_bfloat16* __restrict__ Yh, __nv_bfloat16* __restrict__ Yl) {
    extern __shared__ char dsm[];
    const uint32_t sb = smem_u32(dsm);
    float* dsm_f = (float*)dsm;
    const int tid = threadIdx.x;
    const int wid = tid >> 5, lane = tid & 31;
    const int stile = blockIdx.x, h = blockIdx.y, b = blockIdx.z;
    const int bh = b * HH + h;
    const int s0 = stile * 128;

    auto issue_q = [&](int c) {
        const uint32_t st = sb + OM_Q + (c & 1) * OM_QSTG;
#pragma unroll
        for (int q = 0; q < 2; ++q) {
            const int idx = tid * 2 + q;
            const int r = idx >> 2, cc = idx & 3;
            const __nv_bfloat16* ph = Qph + ((size_t)bh * SS + s0 + r) * FF + c * 32 + cc * 8;
            const __nv_bfloat16* pl = Qpl + ((size_t)bh * SS + s0 + r) * FF + c * 32 + cc * 8;
            cp_async16(st + (uint32_t)r * OM_QS + cc * 16, ph);
            cp_async16(st + 10240 + (uint32_t)r * OM_QS + cc * 16, pl);
        }
        asm volatile("cp.async.commit_group;" ::: "memory");
    };

    // kv resident load (own group)
    {
        const __nv_bfloat16* ph = KVh + (size_t)bh * FF * HD + tid * HD;
        const __nv_bfloat16* pl = KVl + (size_t)bh * FF * HD + tid * HD;
        const uint32_t so = sb + (uint32_t)tid * OM_KVS;
#pragma unroll
        for (int q = 0; q < 8; ++q) {
            cp_async16(so + q * 16, ph + q * 8);
            cp_async16(so + OM_KVL + q * 16, pl + q * 8);
        }
        asm volatile("cp.async.commit_group;" ::: "memory");
    }
    if (tid < 64) {
        float4 kk = *(const float4*)(ksum + (size_t)bh * FF + tid * 4);
        *(float4*)((char*)dsm + OM_KSUM + tid * 16) = kk;
    }
    issue_q(0);
    issue_q(1);

    float acc[8][4];
#pragma unroll
    for (int j = 0; j < 8; ++j)
#pragma unroll
        for (int q = 0; q < 4; ++q) acc[j][q] = 0.0f;
    float dacc = 0.0f;

    const int lrow = lane & 15, lch = (lane >> 4) * 16;

    for (int c = 0; c < 8; ++c) {
        if (c < 7) { asm volatile("cp.async.wait_group 1;" ::: "memory"); }
        else       { asm volatile("cp.async.wait_group 0;" ::: "memory"); }
        __syncthreads();
        const uint32_t qst = sb + OM_Q + (c & 1) * OM_QSTG;

        // denom partial
        if (tid < 128) {
            const float* ksp = (const float*)((char*)dsm + OM_KSUM) + c * 32;
            const uint32_t rh = qst + (uint32_t)tid * OM_QS;
#pragma unroll 8
            for (int f = 0; f < 32; ++f) {
                __nv_bfloat16 vh_, vl_;
                asm volatile("ld.shared.b16 %0, [%1];" : "=h"(*(uint16_t*)&vh_)
                             : "r"(rh + f * 2));
                asm volatile("ld.shared.b16 %0, [%1];" : "=h"(*(uint16_t*)&vl_)
                             : "r"(rh + 10240 + f * 2));
                dacc += (__bfloat162float(vh_) + __bfloat162float(vl_)) * ksp[f];
            }
        }

#pragma unroll
        for (int ks = 0; ks < 2; ++ks) {
            uint32_t ah[4], al[4];
            uint32_t ad = qst + (uint32_t)(wid * 16 + lrow) * OM_QS + lch + ks * 32;
            ldm_x4(ah[0], ah[1], ah[2], ah[3], ad);
            ldm_x4(al[0], al[1], al[2], al[3], ad + 10240);
#pragma unroll
            for (int dg = 0; dg < 4; ++dg) {
                uint32_t bh4[4], bl4[4];
                uint32_t bd = taddr(sb + OM_KVH, OM_KVS, c * 32 + ks * 16, dg * 16, lane);
                ldm_x4_t(bh4[0], bh4[1], bh4[2], bh4[3], bd);
                ldm_x4_t(bl4[0], bl4[1], bl4[2], bl4[3], bd + OM_KVL);
#pragma unroll
                for (int sel = 0; sel < 2; ++sel) {
                    const int j = dg * 2 + sel;
                    mma16816(acc[j], ah[0], ah[1], ah[2], ah[3], bh4[sel], bh4[sel + 2]);
                    mma16816(acc[j], al[0], al[1], al[2], al[3], bh4[sel], bh4[sel + 2]);
                    mma16816(acc[j], ah[0], ah[1], ah[2], ah[3], bl4[sel], bl4[sel + 2]);
                }
            }
        }
        __syncthreads();
        if (c + 2 < 8) issue_q(c + 2);   // AFTER consumption barrier (race fix)
    }

    if (tid < 128) dsm_f[OM_DEN / 4 + tid] = dacc;
    __syncthreads();

    const int r0 = wid * 16 + (lane >> 2);
    const float inv0 = 1.0f / (dsm_f[OM_DEN / 4 + r0] + 1e-8f);
    const float inv1 = 1.0f / (dsm_f[OM_DEN / 4 + r0 + 8] + 1e-8f);
#pragma unroll
    for (int j = 0; j < 8; ++j) {
        const int col = h * HD + j * 8 + (lane & 3) * 2;
        float o00 = acc[j][0] * inv0, o01 = acc[j][1] * inv0;
        float o10 = acc[j][2] * inv1, o11 = acc[j][3] * inv1;
        __nv_bfloat16 h0, l0, h1, l1;
        size_t off0 = ((size_t)(b * SS + s0 + r0)) * DD + col;
        size_t off1 = ((size_t)(b * SS + s0 + r0 + 8)) * DD + col;
        split2(o00, h0, l0); split2(o01, h1, l1);
        *(__nv_bfloat162*)(Yh + off0) = __nv_bfloat162(h0, h1);
        *(__nv_bfloat162*)(Yl + off0) = __nv_bfloat162(l0, l1);
        split2(o10, h0, l0); split2(o11, h1, l1);
        *(__nv_bfloat162*)(Yh + off1) = __nv_bfloat162(h0, h1);
        *(__nv_bfloat162*)(Yl + off1) = __nv_bfloat162(l0, l1);
    }
}

// ---------------------------------------------------------------------------
// split fp32 -> (bf16 hi, bf16 lo) ; zero
// ---------------------------------------------------------------------------
__global__ void __launch_bounds__(256)
split_bf16(const float* __restrict__ in, __nv_bfloat16* __restrict__ hi,
           __nv_bfloat16* __restrict__ lo, int n) {
    int i = (blockIdx.x * 256 + threadIdx.x) * 4;
    if (i >= n) return;
    float4 v = *(const float4*)(in + i);
    float a[4] = {v.x, v.y, v.z, v.w};
    __nv_bfloat16 h[4], l[4];
#pragma unroll
    for (int j = 0; j < 4; ++j) split2(a[j], h[j], l[j]);
    *(__nv_bfloat162*)(hi + i)     = __nv_bfloat162(h[0], h[1]);
    *(__nv_bfloat162*)(hi + i + 2) = __nv_bfloat162(h[2], h[3]);
    *(__nv_bfloat162*)(lo + i)     = __nv_bfloat162(l[0], l[1]);
    *(__nv_bfloat162*)(lo + i + 2) = __nv_bfloat162(l[2], l[3]);
}
__global__ void zero_kernel(float* __restrict__ p, int n) {
    int i = blockIdx.x * blockDim.x + threadIdx.x;
    if (i < n) p[i] = 0.0f;
}

// ---------------------------------------------------------------------------
// launch
// ---------------------------------------------------------------------------
extern "C" void kernel_launch(void* const* d_in, const int* in_sizes, int n_in,
                              void* d_out, int out_size) {
    const float* x  = (const float*)d_in[0];
    const float* Wq = (const float*)d_in[1];
    const float* bq = (const float*)d_in[2];
    const float* Wk = (const float*)d_in[3];
    const float* bk = (const float*)d_in[4];
    const float* Wv = (const float*)d_in[5];
    const float* bv = (const float*)d_in[6];
    const float* Wo = (const float*)d_in[7];
    const float* bo = (const float*)d_in[8];
    const float* rf = (const float*)d_in[9];
    float* out = (float*)d_out;

    __nv_bfloat16 *pxh, *pxl, *pwh, *pwl, *prfh, *prfl;
    __nv_bfloat16 *pqh, *pql, *pkh, *pkl, *pvh, *pvl, *pyh, *pyl;
    __nv_bfloat16 *pqph, *pqpl, *pkph, *pkpl, *pkvh, *pkvl;
    float *pkv, *pks;
    cudaGetSymbolAddress((void**)&pxh, g_xh);
    cudaGetSymbolAddress((void**)&pxl, g_xl);
    cudaGetSymbolAddress((void**)&pwh, g_wh);
    cudaGetSymbolAddress((void**)&pwl, g_wl);
    cudaGetSymbolAddress((void**)&prfh, g_rfh);
    cudaGetSymbolAddress((void**)&prfl, g_rfl);
    cudaGetSymbolAddress((void**)&pqh, g_qh);
    cudaGetSymbolAddress((void**)&pql, g_ql);
    cudaGetSymbolAddress((void**)&pkh, g_kh);
    cudaGetSymbolAddress((void**)&pkl, g_kl);
    cudaGetSymbolAddress((void**)&pvh, g_vh);
    cudaGetSymbolAddress((void**)&pvl, g_vl);
    cudaGetSymbolAddress((void**)&pyh, g_yh);
    cudaGetSymbolAddress((void**)&pyl, g_yl);
    cudaGetSymbolAddress((void**)&pqph, g_qph);
    cudaGetSymbolAddress((void**)&pqpl, g_qpl);
    cudaGetSymbolAddress((void**)&pkph, g_kph);
    cudaGetSymbolAddress((void**)&pkpl, g_kpl);
    cudaGetSymbolAddress((void**)&pkvh, g_kvh);
    cudaGetSymbolAddress((void**)&pkvl, g_kvl);
    cudaGetSymbolAddress((void**)&pkv, g_kv);
    cudaGetSymbolAddress((void**)&pks, g_ksum);

    cudaFuncSetAttribute(gemm_mma_f32, cudaFuncAttributeMaxDynamicSharedMemorySize, GEMM_DSMEM);
    cudaFuncSetAttribute(gemm_mma_split, cudaFuncAttributeMaxDynamicSharedMemorySize, GEMM_DSMEM);
    cudaFuncSetAttribute(phi_mma, cudaFuncAttributeMaxDynamicSharedMemorySize, PH_DSMEM);
    cudaFuncSetAttribute(kv_mma, cudaFuncAttributeMaxDynamicSharedMemorySize, KV_DSMEM);
    cudaFuncSetAttribute(out_mma, cudaFuncAttributeMaxDynamicSharedMemorySize, OM_DSMEM);

    const int WSZ = DD * DD;

    split_bf16<<<NN * DD / 4 / 256, 256>>>(x, pxh, pxl, NN * DD);
    split_bf16<<<WSZ / 4 / 256, 256>>>(Wq, pwh + 0 * WSZ, pwl + 0 * WSZ, WSZ);
    split_bf16<<<WSZ / 4 / 256, 256>>>(Wk, pwh + 1 * WSZ, pwl + 1 * WSZ, WSZ);
    split_bf16<<<WSZ / 4 / 256, 256>>>(Wv, pwh + 2 * WSZ, pwl + 2 * WSZ, WSZ);
    split_bf16<<<WSZ / 4 / 256, 256>>>(Wo, pwh + 3 * WSZ, pwl + 3 * WSZ, WSZ);
    split_bf16<<<HH * HD * FF / 4 / 256, 256>>>(rf, prfh, prfl, HH * HD * FF);

    dim3 gg(DD / 128, NN / 128);
    gemm_mma_split<<<gg, 256, GEMM_DSMEM>>>(pxh, pxl, pwh + 0 * WSZ, pwl + 0 * WSZ, bq, pqh, pql, DD);
    gemm_mma_split<<<gg, 256, GEMM_DSMEM>>>(pxh, pxl, pwh + 1 * WSZ, pwl + 1 * WSZ, bk, pkh, pkl, DD);
    gemm_mma_split<<<gg, 256, GEMM_DSMEM>>>(pxh, pxl, pwh + 2 * WSZ, pwl + 2 * WSZ, bv, pvh, pvl, DD);

    dim3 pg(SS / 128, 2, BB * HH);
    phi_mma<<<pg, 256, PH_DSMEM>>>(pqh, pql, prfh, prfl, pqph, pqpl);
    phi_mma<<<pg, 256, PH_DSMEM>>>(pkh, pkl, prfh, prfl, pkph, pkpl);

    zero_kernel<<<(BB * HH * FF * HD + 255) / 256, 256>>>(pkv, BB * HH * FF * HD);
    zero_kernel<<<(BB * HH * FF + 255) / 256, 256>>>(pks, BB * HH * FF);

    kv_mma<<<dim3(8, HH, BB), 256, KV_DSMEM>>>(pkph, pkpl, pvh, pvl, pkv, pks);

    split_bf16<<<BB * HH * FF * HD / 4 / 256, 256>>>(pkv, pkvh, pkvl, BB * HH * FF * HD);

    out_mma<<<dim3(SS / 128, HH, BB), 256, OM_DSMEM>>>(pqph, pqpl, pkvh, pkvl, pks, pyh, pyl);

    gemm_mma_f32<<<gg, 256, GEMM_DSMEM>>>(pyh, pyl, pwh + 3 * WSZ, pwl + 3 * WSZ, bo, out, DD);
}